// round 9
// baseline (speedup 1.0000x reference)
#include <cuda_runtime.h>
#include <math.h>
#include <cstdint>

#define DIM 768
#define HEADS 12
#define HEAD_DIM 64
#define BATCH 4
#define SEQ 2048
#define QKV_DIM (3 * DIM)
#define QSCALE 0.18033688011112042f  /* 0.125 * log2(e) */

__device__ float g_qkv[(size_t)BATCH * SEQ * QKV_DIM];
__device__ float g_att[(size_t)BATCH * SEQ * DIM];

__device__ __forceinline__ unsigned f2tf32(float x) {
    unsigned u;
    asm("cvt.rna.tf32.f32 %0, %1;" : "=r"(u) : "f"(x));
    return u;
}
__device__ __forceinline__ float ex2(float x) {
    float y;
    asm("ex2.approx.f32 %0, %1;" : "=f"(y) : "f"(x));
    return y;
}
__device__ __forceinline__ void mma_tf32(float c[4], const unsigned a[4],
                                         unsigned b0, unsigned b1) {
    asm volatile(
        "mma.sync.aligned.m16n8k8.row.col.f32.tf32.tf32.f32 "
        "{%0,%1,%2,%3}, {%4,%5,%6,%7}, {%8,%9}, {%0,%1,%2,%3};"
        : "+f"(c[0]), "+f"(c[1]), "+f"(c[2]), "+f"(c[3])
        : "r"(a[0]), "r"(a[1]), "r"(a[2]), "r"(a[3]), "r"(b0), "r"(b1));
}

#define BAR_SYNC(id)   asm volatile("bar.sync %0, 256;" :: "r"(id) : "memory")
#define BAR_ARRIVE(id) asm volatile("bar.arrive %0, 256;" :: "r"(id) : "memory")

// ===========================================================================
// TF32 GEMM (NT) v6: warp-specialized. C = A[M,K]*B[N,K]^T + bias.
// 256 threads: warps 0-3 consumers (v3 geometry: 2x2 warps, 64x64 tile,
// mt=4, nt=8), threads 128-255 producers (LDG -> cvt -> pair-packed STS).
// 4-stage smem ring, named-barrier FULL(1+s)/FREE(5+s) handshake.
// ===========================================================================
#define GSA 136
#define GSB 40
#define G_ASIZE (16 * GSA)           // 2176 words
#define G_BSIZE (128 * GSB)          // 5120 words
#define G_BUF (G_ASIZE + G_BSIZE)    // 7296 words/stage
#define NSTAGE 4
#define GEMM_SMEM_B (NSTAGE * G_BUF * 4)  // 116736 B

extern __shared__ unsigned dyn_smem[];

__global__ __launch_bounds__(256) void gemm_tf32_ws(
    const float* __restrict__ A, const float* __restrict__ B,
    const float* __restrict__ bias, float* __restrict__ C,
    int M, int N, int K) {
    const int tid = threadIdx.x;
    const int lane = tid & 31;
    const int wid = tid >> 5;
    const int bx = blockIdx.x, by = blockIdx.y;
    const int NT = K / 16;

    if (wid < 4) {
        // ---------------- consumers ----------------
        const int wm = wid & 1, wn = wid >> 1;
        const int r0 = lane >> 2, q4 = lane & 3;

        float acc[4][8][4];
#pragma unroll
        for (int i = 0; i < 4; i++)
#pragma unroll
            for (int j = 0; j < 8; j++)
#pragma unroll
                for (int e = 0; e < 4; e++) acc[i][j][e] = 0.f;

        for (int t = 0; t < NT; t++) {
            const int s = t & (NSTAGE - 1);
            BAR_SYNC(1 + s);  // wait FULL
            const unsigned* As = dyn_smem + s * G_BUF;
            const unsigned* Bs = As + G_ASIZE;
#pragma unroll
            for (int kc = 0; kc < 2; kc++) {
                const int kr = kc * 8 + q4;
                unsigned af[4][4];
#pragma unroll
                for (int mt = 0; mt < 4; mt++) {
                    const int j = (wm * 4 + mt) * 16 + r0 * 2;
                    uint2 p0 = *(const uint2*)&As[kr * GSA + j];
                    uint2 p1 = *(const uint2*)&As[(kr + 4) * GSA + j];
                    af[mt][0] = p0.x; af[mt][1] = p0.y;
                    af[mt][2] = p1.x; af[mt][3] = p1.y;
                }
#pragma unroll
                for (int nt = 0; nt < 8; nt++) {
                    const int n = wn * 64 + nt * 8 + r0;
                    uint2 bb = *(const uint2*)&Bs[n * GSB + kc * 8 + q4 * 2];
#pragma unroll
                    for (int mt = 0; mt < 4; mt++)
                        mma_tf32(acc[mt][nt], af[mt], bb.x, bb.y);
                }
            }
            BAR_ARRIVE(5 + s);  // signal FREE
        }

        // epilogue
#pragma unroll
        for (int nt = 0; nt < 8; nt++) {
            const int col = bx * 128 + wn * 64 + nt * 8 + 2 * q4;
            const float bv0 = __ldg(&bias[col]);
            const float bv1 = __ldg(&bias[col + 1]);
#pragma unroll
            for (int mt = 0; mt < 4; mt++) {
                const int row = by * 128 + wm * 64 + mt * 16 + r0;
                *(float2*)&C[(size_t)row * N + col] =
                    make_float2(acc[mt][nt][0] + bv0, acc[mt][nt][1] + bv1);
                *(float2*)&C[(size_t)(row + 8) * N + col] =
                    make_float2(acc[mt][nt][2] + bv0, acc[mt][nt][3] + bv1);
            }
        }
    } else {
        // ---------------- producers ----------------
        const int ptid = tid - 128;
        const int ap = ptid >> 1, ag = ap >> 3, ar = ap & 7;
        const int ak = (ptid & 1) * 8;
        const int jA = ag * 16 + ar * 2;
        const float* Ag = A + (size_t)(by * 128 + ag * 16 + ar) * K + ak;
        const float* Bg = B + (size_t)(bx * 128 + ptid) * K;
        const size_t arow8 = (size_t)8 * K;

        for (int t = 0; t < NT; t++) {
            const int s = t & (NSTAGE - 1);
            if (t >= NSTAGE) BAR_SYNC(5 + s);  // wait FREE
            const float* ap0 = Ag + t * 16;
            const float* bp0 = Bg + t * 16;
            float4 a0 = *(const float4*)ap0;
            float4 a1 = *(const float4*)(ap0 + 4);
            float4 c0 = *(const float4*)(ap0 + arow8);
            float4 c1 = *(const float4*)(ap0 + arow8 + 4);
            float4 w0 = *(const float4*)bp0;
            float4 w1 = *(const float4*)(bp0 + 4);
            float4 w2 = *(const float4*)(bp0 + 8);
            float4 w3 = *(const float4*)(bp0 + 12);

            unsigned* As = dyn_smem + s * G_BUF;
            unsigned* Bs = As + G_ASIZE;
            float ua[8] = {a0.x, a0.y, a0.z, a0.w, a1.x, a1.y, a1.z, a1.w};
            float va[8] = {c0.x, c0.y, c0.z, c0.w, c1.x, c1.y, c1.z, c1.w};
#pragma unroll
            for (int i = 0; i < 8; i++) {
                uint2 tt;
                tt.x = f2tf32(ua[i]);
                tt.y = f2tf32(va[i]);
                *(uint2*)&As[(ak + i) * GSA + jA] = tt;
            }
            float fb[16] = {w0.x, w0.y, w0.z, w0.w, w1.x, w1.y, w1.z, w1.w,
                            w2.x, w2.y, w2.z, w2.w, w3.x, w3.y, w3.z, w3.w};
#pragma unroll
            for (int kb = 0; kb < 2; kb++)
#pragma unroll
                for (int qq = 0; qq < 4; qq++) {
                    uint2 tt;
                    tt.x = f2tf32(fb[kb * 8 + qq]);
                    tt.y = f2tf32(fb[kb * 8 + qq + 4]);
                    *(uint2*)&Bs[ptid * GSB + kb * 8 + qq * 2] = tt;
                }
            BAR_ARRIVE(1 + s);  // signal FULL
        }
    }
}

// ===========================================================================
// TF32 flash attention v5: double-buffered K/V stages (1 sync/tile); K/V
// global loads for tile t+1 issued after softmax (sc regs dead) so their
// latency hides under the PV mma phase. Same fragment geometry as v3/v4.
// ===========================================================================
#define KS 72
#define PS 136
#define F_KV (2 * 64 * KS)               // 9216 words per stage (K + V)
#define F_PB (2 * F_KV)                  // P buffer base (18432 words)
#define F_WORDS (F_PB + 8 * 8 * PS)      // 27136 words = 108544 B

__global__ __launch_bounds__(128) void flash_tf32_v5(
    const float* __restrict__ qkv, float* __restrict__ out) {
    const int tid = threadIdx.x;
    const int lane = tid & 31;
    const int wid = tid >> 5;
    const int r0 = lane >> 2, q4 = lane & 3;
    const int qt = blockIdx.x, h = blockIdx.y, b = blockIdx.z;
    unsigned* pw = dyn_smem + F_PB + wid * (2 * 8 * PS);

    const size_t base = (size_t)b * SEQ * QKV_DIM;

    unsigned qa[2][8][4];
#pragma unroll
    for (int mt = 0; mt < 2; mt++) {
        const int row = qt * 128 + wid * 32 + mt * 16 + r0;
        const float* p0 = qkv + base + (size_t)row * QKV_DIM + h * HEAD_DIM + q4;
        const float* p1 = p0 + (size_t)8 * QKV_DIM;
#pragma unroll
        for (int kc = 0; kc < 8; kc++) {
            qa[mt][kc][0] = f2tf32(p0[kc * 8] * QSCALE);
            qa[mt][kc][1] = f2tf32(p1[kc * 8] * QSCALE);
            qa[mt][kc][2] = f2tf32(p0[kc * 8 + 4] * QSCALE);
            qa[mt][kc][3] = f2tf32(p1[kc * 8 + 4] * QSCALE);
        }
    }

    float o[2][8][4];
#pragma unroll
    for (int mt = 0; mt < 2; mt++)
#pragma unroll
        for (int nc = 0; nc < 8; nc++)
#pragma unroll
            for (int e = 0; e < 4; e++) o[mt][nc][e] = 0.f;
    float mA[2] = {-1e30f, -1e30f}, mB[2] = {-1e30f, -1e30f};
    float lA[2] = {0.f, 0.f}, lB[2] = {0.f, 0.f};

    // loader mappings
    const int kkey = tid >> 1;
    const int kc0 = (tid & 1) * 32;
    const int vpr = tid >> 2;
    const int vkb = vpr >> 2, vq = vpr & 3;
    const int vr0 = vkb * 8 + vq;
    const int vcs = (tid & 3) * 16;

    float kf[32], vlo[16], vhi[16];

    auto load_kv = [&](int kt) {
        const float* kg = qkv + base + (size_t)(kt * 64 + kkey) * QKV_DIM
                          + DIM + h * HEAD_DIM + kc0;
#pragma unroll
        for (int i = 0; i < 8; i++) {
            float4 t = *(const float4*)(kg + i * 4);
            kf[i * 4 + 0] = t.x; kf[i * 4 + 1] = t.y;
            kf[i * 4 + 2] = t.z; kf[i * 4 + 3] = t.w;
        }
        const float* vgl = qkv + base + (size_t)(kt * 64 + vr0) * QKV_DIM
                           + 2 * DIM + h * HEAD_DIM + vcs;
        const float* vgh = vgl + (size_t)4 * QKV_DIM;
#pragma unroll
        for (int i = 0; i < 4; i++) {
            float4 a = *(const float4*)(vgl + i * 4);
            float4 c = *(const float4*)(vgh + i * 4);
            vlo[i * 4 + 0] = a.x; vlo[i * 4 + 1] = a.y;
            vlo[i * 4 + 2] = a.z; vlo[i * 4 + 3] = a.w;
            vhi[i * 4 + 0] = c.x; vhi[i * 4 + 1] = c.y;
            vhi[i * 4 + 2] = c.z; vhi[i * 4 + 3] = c.w;
        }
    };
    auto sts_kv = [&](int s) {
        unsigned* ks2 = dyn_smem + s * F_KV;
        unsigned* vp = ks2 + 64 * KS;
#pragma unroll
        for (int kb = 0; kb < 4; kb++)
#pragma unroll
            for (int qq = 0; qq < 4; qq++) {
                uint2 t;
                t.x = f2tf32(kf[kb * 8 + qq]);
                t.y = f2tf32(kf[kb * 8 + qq + 4]);
                *(uint2*)&ks2[kkey * KS + kc0 + kb * 8 + qq * 2] = t;
            }
#pragma unroll
        for (int i = 0; i < 16; i++) {
            uint2 t;
            t.x = f2tf32(vlo[i]);
            t.y = f2tf32(vhi[i]);
            *(uint2*)&vp[(vcs + i) * KS + vkb * 8 + vq * 2] = t;
        }
    };

    const int NT = SEQ / 64;
    load_kv(0);
    sts_kv(0);
    __syncthreads();

    for (int kt = 0; kt < NT; kt++) {
        const unsigned* ks2 = dyn_smem + (kt & 1) * F_KV;
        const unsigned* vp = ks2 + 64 * KS;

        // ---- S = Q*K^T ----
        float sc[2][8][4];
#pragma unroll
        for (int nc = 0; nc < 8; nc++)
#pragma unroll
            for (int e = 0; e < 4; e++) { sc[0][nc][e] = 0.f; sc[1][nc][e] = 0.f; }
#pragma unroll
        for (int kc = 0; kc < 8; kc++) {
#pragma unroll
            for (int nc = 0; nc < 8; nc++) {
                const int key = nc * 8 + r0;
                uint2 kk = *(const uint2*)&ks2[key * KS + kc * 8 + q4 * 2];
                mma_tf32(sc[0][nc], qa[0][kc], kk.x, kk.y);
                mma_tf32(sc[1][nc], qa[1][kc], kk.x, kk.y);
            }
        }

        // ---- online softmax + P store ----
#pragma unroll
        for (int mt = 0; mt < 2; mt++) {
            float tA = -1e30f, tB = -1e30f;
#pragma unroll
            for (int nc = 0; nc < 8; nc++) {
                tA = fmaxf(tA, fmaxf(sc[mt][nc][0], sc[mt][nc][1]));
                tB = fmaxf(tB, fmaxf(sc[mt][nc][2], sc[mt][nc][3]));
            }
            tA = fmaxf(tA, __shfl_xor_sync(0xffffffffu, tA, 1));
            tA = fmaxf(tA, __shfl_xor_sync(0xffffffffu, tA, 2));
            tB = fmaxf(tB, __shfl_xor_sync(0xffffffffu, tB, 1));
            tB = fmaxf(tB, __shfl_xor_sync(0xffffffffu, tB, 2));
            const float mnA = fmaxf(mA[mt], tA);
            const float mnB = fmaxf(mB[mt], tB);
            const float cA = ex2(mA[mt] - mnA);
            const float cB = ex2(mB[mt] - mnB);
            mA[mt] = mnA; mB[mt] = mnB;
            lA[mt] *= cA; lB[mt] *= cB;
#pragma unroll
            for (int nc = 0; nc < 8; nc++) {
                o[mt][nc][0] *= cA; o[mt][nc][1] *= cA;
                o[mt][nc][2] *= cB; o[mt][nc][3] *= cB;
                const float p0 = ex2(sc[mt][nc][0] - mnA);
                const float p1 = ex2(sc[mt][nc][1] - mnA);
                const float p2 = ex2(sc[mt][nc][2] - mnB);
                const float p3 = ex2(sc[mt][nc][3] - mnB);
                lA[mt] += p0 + p1; lB[mt] += p2 + p3;
                uint4 stv;
                stv.x = f2tf32(p0); stv.y = f2tf32(p2);
                stv.z = f2tf32(p1); stv.w = f2tf32(p3);
                *(uint4*)&pw[(mt * 8 + r0) * PS + (nc * 8 + 2 * q4) * 2] = stv;
            }
        }
        __syncwarp();

        // ---- prefetch next K/V tile (latency hidden by PV below) ----
        if (kt + 1 < NT) load_kv(kt + 1);

        // ---- O += P*V ----
#pragma unroll
        for (int kb = 0; kb < 8; kb++) {
            unsigned af[2][4];
#pragma unroll
            for (int mt = 0; mt < 2; mt++) {
                const unsigned* pr = &pw[(mt * 8 + r0) * PS + (kb * 8 + q4) * 2];
                uint2 a0 = *(const uint2*)pr;
                uint2 a1 = *(const uint2*)(pr + 8);
                af[mt][0] = a0.x; af[mt][1] = a0.y;
                af[mt][2] = a1.x; af[mt][3] = a1.y;
            }
#pragma unroll
            for (int nc = 0; nc < 8; nc++) {
                uint2 vv = *(const uint2*)&vp[(nc * 8 + r0) * KS + kb * 8 + q4 * 2];
                mma_tf32(o[0][nc], af[0], vv.x, vv.y);
                mma_tf32(o[1][nc], af[1], vv.x, vv.y);
            }
        }

        if (kt + 1 < NT) sts_kv((kt + 1) & 1);
        __syncthreads();
    }

    // ---- epilogue ----
#pragma unroll
    for (int mt = 0; mt < 2; mt++) {
        float la = lA[mt], lb = lB[mt];
        la += __shfl_xor_sync(0xffffffffu, la, 1);
        la += __shfl_xor_sync(0xffffffffu, la, 2);
        lb += __shfl_xor_sync(0xffffffffu, lb, 1);
        lb += __shfl_xor_sync(0xffffffffu, lb, 2);
        const float ia = 1.f / la, ib = 1.f / lb;
        const int row = qt * 128 + wid * 32 + mt * 16 + r0;
        float* oA = out + ((size_t)b * SEQ + row) * DIM + h * HEAD_DIM;
        float* oB = oA + (size_t)8 * DIM;
#pragma unroll
        for (int nc = 0; nc < 8; nc++) {
            const int col = nc * 8 + 2 * q4;
            *(float2*)(oA + col) = make_float2(o[mt][nc][0] * ia, o[mt][nc][1] * ia);
            *(float2*)(oB + col) = make_float2(o[mt][nc][2] * ib, o[mt][nc][3] * ib);
        }
    }
}

// ===========================================================================
extern "C" void kernel_launch(void* const* d_in, const int* in_sizes, int n_in,
                              void* d_out, int out_size) {
    const float* x      = (const float*)d_in[0];
    const float* w_qkv  = (const float*)d_in[1];
    const float* b_qkv  = (const float*)d_in[2];
    const float* w_proj = (const float*)d_in[3];
    const float* b_proj = (const float*)d_in[4];
    float* out = (float*)d_out;

    float* qkv = nullptr;
    float* att = nullptr;
    cudaGetSymbolAddress((void**)&qkv, g_qkv);
    cudaGetSymbolAddress((void**)&att, g_att);

    const int M = BATCH * SEQ;               // 8192
    const int FA_SMEM = F_WORDS * 4;         // 108544 B

    cudaFuncSetAttribute(gemm_tf32_ws, cudaFuncAttributeMaxDynamicSharedMemorySize,
                         GEMM_SMEM_B);
    cudaFuncSetAttribute(flash_tf32_v5, cudaFuncAttributeMaxDynamicSharedMemorySize,
                         FA_SMEM);

    {
        dim3 grid(QKV_DIM / 128, M / 128);   // (18, 64)
        gemm_tf32_ws<<<grid, 256, GEMM_SMEM_B>>>(x, w_qkv, b_qkv, qkv, M, QKV_DIM, DIM);
    }
    {
        dim3 grid(SEQ / 128, HEADS, BATCH);  // (16, 12, 4)
        flash_tf32_v5<<<grid, 128, FA_SMEM>>>(qkv, att);
    }
    {
        dim3 grid(DIM / 128, M / 128);       // (6, 64)
        gemm_tf32_ws<<<grid, 256, GEMM_SMEM_B>>>(att, w_proj, b_proj, out, M, DIM, DIM);
    }
}

// round 10
// speedup vs baseline: 1.3515x; 1.3515x over previous
#include <cuda_runtime.h>
#include <cuda_fp16.h>
#include <math.h>
#include <cstdint>

#define DIM 768
#define HEADS 12
#define HEAD_DIM 64
#define BATCH 4
#define SEQ 2048
#define QKV_DIM (3 * DIM)
#define QSCALE 0.18033688011112042f  /* 0.125 * log2(e) */

__device__ float g_qkv[(size_t)BATCH * SEQ * QKV_DIM];
__device__ float g_att[(size_t)BATCH * SEQ * DIM];

__device__ __forceinline__ float ex2(float x) {
    float y;
    asm("ex2.approx.f32 %0, %1;" : "=f"(y) : "f"(x));
    return y;
}
__device__ __forceinline__ unsigned h2pack(float a, float b) {
    __half2 h = __floats2half2_rn(a, b);
    return *reinterpret_cast<unsigned*>(&h);
}
__device__ __forceinline__ uint32_t smem_u32(const void* p) {
    uint32_t a;
    asm("{ .reg .u64 t; cvta.to.shared.u64 t, %1; cvt.u32.u64 %0, t; }"
        : "=r"(a) : "l"(p));
    return a;
}
__device__ __forceinline__ void mma_fp16(float c[4], const unsigned a[4],
                                         unsigned b0, unsigned b1) {
    asm volatile(
        "mma.sync.aligned.m16n8k16.row.col.f32.f16.f16.f32 "
        "{%0,%1,%2,%3}, {%4,%5,%6,%7}, {%8,%9}, {%0,%1,%2,%3};"
        : "+f"(c[0]), "+f"(c[1]), "+f"(c[2]), "+f"(c[3])
        : "r"(a[0]), "r"(a[1]), "r"(a[2]), "r"(a[3]), "r"(b0), "r"(b1));
}
__device__ __forceinline__ void ldsm4(unsigned r[4], uint32_t addr) {
    asm volatile("ldmatrix.sync.aligned.m8n8.x4.shared.b16 {%0,%1,%2,%3}, [%4];"
                 : "=r"(r[0]), "=r"(r[1]), "=r"(r[2]), "=r"(r[3]) : "r"(addr));
}
__device__ __forceinline__ void ldsm4t(unsigned r[4], uint32_t addr) {
    asm volatile("ldmatrix.sync.aligned.m8n8.x4.trans.shared.b16 {%0,%1,%2,%3}, [%4];"
                 : "=r"(r[0]), "=r"(r[1]), "=r"(r[2]), "=r"(r[3]) : "r"(addr));
}

// ===========================================================================
// FP16 GEMM (NT): C[M,N] = A[M,K]*B[N,K]^T + bias (fp32 accum).
// 128x128 CTA tile, BK=16, 128 threads = 4 warps (2m x 2n), warp 64x64.
// smem: row-major half rows (8 u32 words, stride 12 -> conflict-free ldmatrix).
// Double-buffered with register prefetch; 1 syncthreads per k-tile.
// ===========================================================================
#define GS 12                      // row stride in u32 words
#define G_HALF (128 * GS)          // 1536 words per matrix
#define G_BUF2 (2 * G_HALF)        // 3072 words per stage
#define GEMM_SMEM_B (2 * G_BUF2 * 4)  // 24576 bytes

extern __shared__ unsigned dyn_smem[];

__global__ __launch_bounds__(128) void gemm_fp16(
    const float* __restrict__ A, const float* __restrict__ B,
    const float* __restrict__ bias, float* __restrict__ C,
    int M, int N, int K) {
    const int tid = threadIdx.x;
    const int lane = tid & 31;
    const int wid = tid >> 5;
    const int wm = wid & 1, wn = wid >> 1;
    const int bx = blockIdx.x, by = blockIdx.y;
    const int r0 = lane >> 2, q4 = lane & 3;
    const uint32_t sbase = smem_u32(dyn_smem);

    // ldmatrix lane-address components (row within 16-block, col-word offset)
    const int lrow = (lane & 7) + ((lane >> 3) & 1) * 8;
    const int lcw = (lane >> 4) * 4;

    const float* Ag = A + (size_t)(by * 128 + tid) * K;
    const float* Bg = B + (size_t)(bx * 128 + tid) * K;

    float st[32];
    {
        const float4* a4 = (const float4*)Ag;
        const float4* b4 = (const float4*)Bg;
#pragma unroll
        for (int i = 0; i < 4; i++) {
            float4 v = a4[i];
            st[i * 4 + 0] = v.x; st[i * 4 + 1] = v.y;
            st[i * 4 + 2] = v.z; st[i * 4 + 3] = v.w;
            float4 w = b4[i];
            st[16 + i * 4 + 0] = w.x; st[16 + i * 4 + 1] = w.y;
            st[16 + i * 4 + 2] = w.z; st[16 + i * 4 + 3] = w.w;
        }
    }

    float acc[4][8][4];
#pragma unroll
    for (int i = 0; i < 4; i++)
#pragma unroll
        for (int j = 0; j < 8; j++)
#pragma unroll
            for (int e = 0; e < 4; e++) acc[i][j][e] = 0.f;

    auto store_tile = [&](unsigned* s) {
        unsigned* As = s;
        unsigned* Bs = s + G_HALF;
        unsigned aw[8], bw[8];
#pragma unroll
        for (int w = 0; w < 8; w++) {
            aw[w] = h2pack(st[2 * w], st[2 * w + 1]);
            bw[w] = h2pack(st[16 + 2 * w], st[16 + 2 * w + 1]);
        }
        *(uint4*)&As[tid * GS]     = make_uint4(aw[0], aw[1], aw[2], aw[3]);
        *(uint4*)&As[tid * GS + 4] = make_uint4(aw[4], aw[5], aw[6], aw[7]);
        *(uint4*)&Bs[tid * GS]     = make_uint4(bw[0], bw[1], bw[2], bw[3]);
        *(uint4*)&Bs[tid * GS + 4] = make_uint4(bw[4], bw[5], bw[6], bw[7]);
    };

    store_tile(dyn_smem);
    __syncthreads();

    const int NT = K / 16;
    for (int t = 0; t < NT; t++) {
        if (t + 1 < NT) {
            const float4* a4 = (const float4*)(Ag + (t + 1) * 16);
            const float4* b4 = (const float4*)(Bg + (t + 1) * 16);
#pragma unroll
            for (int i = 0; i < 4; i++) {
                float4 v = a4[i];
                st[i * 4 + 0] = v.x; st[i * 4 + 1] = v.y;
                st[i * 4 + 2] = v.z; st[i * 4 + 3] = v.w;
                float4 w = b4[i];
                st[16 + i * 4 + 0] = w.x; st[16 + i * 4 + 1] = w.y;
                st[16 + i * 4 + 2] = w.z; st[16 + i * 4 + 3] = w.w;
            }
        }
        {
            const uint32_t stg = sbase + (t & 1) * (G_BUF2 * 4);
            unsigned af[4][4];
#pragma unroll
            for (int mt = 0; mt < 4; mt++) {
                const int m0 = (wm * 4 + mt) * 16;
                ldsm4(af[mt], stg + 4 * ((m0 + lrow) * GS + lcw));
            }
#pragma unroll
            for (int np = 0; np < 4; np++) {
                const int n0 = wn * 64 + np * 16;
                unsigned bf[4];
                ldsm4(bf, stg + 4 * (G_HALF + (n0 + lrow) * GS + lcw));
#pragma unroll
                for (int mt = 0; mt < 4; mt++) {
                    mma_fp16(acc[mt][2 * np], af[mt], bf[0], bf[2]);
                    mma_fp16(acc[mt][2 * np + 1], af[mt], bf[1], bf[3]);
                }
            }
        }
        if (t + 1 < NT) store_tile(dyn_smem + ((t + 1) & 1) * G_BUF2);
        __syncthreads();
    }

    // epilogue
#pragma unroll
    for (int nc = 0; nc < 8; nc++) {
        const int col = bx * 128 + wn * 64 + nc * 8 + 2 * q4;
        const float bv0 = __ldg(&bias[col]);
        const float bv1 = __ldg(&bias[col + 1]);
#pragma unroll
        for (int mt = 0; mt < 4; mt++) {
            const int row = by * 128 + wm * 64 + mt * 16 + r0;
            *(float2*)&C[(size_t)row * N + col] =
                make_float2(acc[mt][nc][0] + bv0, acc[mt][nc][1] + bv1);
            *(float2*)&C[(size_t)(row + 8) * N + col] =
                make_float2(acc[mt][nc][2] + bv0, acc[mt][nc][3] + bv1);
        }
    }
}

// ===========================================================================
// FP16 flash attention. CTA = 128 threads (4 warps), 128 q-rows (warp 32x64,
// mt=2). KV tile = 64 keys. smem row-major half rows, stride 36 words:
//   ks[key][dim]  -> S-phase B-frags via ldmatrix.x4 (non-trans)
//   vs[key][dim]  -> PV   B-frags via ldmatrix.x4.trans (no reg transpose)
//   pw[warp][mt*16+r][key] -> PV A-frags via ldmatrix.x4
// Softmax exp2-domain, fp32; P packed to fp16 on store.
// ===========================================================================
#define FS 36                          // row stride in u32 words
#define F_K (64 * FS)                  // 2304 words
#define F_PW (32 * FS)                 // 1152 words per warp
#define F_WORDS (2 * F_K + 4 * F_PW)   // 9216 words = 36864 B

__global__ __launch_bounds__(128) void flash_fp16(
    const float* __restrict__ qkv, float* __restrict__ out) {
    const int tid = threadIdx.x;
    const int lane = tid & 31;
    const int wid = tid >> 5;
    const int r0 = lane >> 2, q4 = lane & 3;
    const int qt = blockIdx.x, h = blockIdx.y, b = blockIdx.z;
    const uint32_t fbase = smem_u32(dyn_smem);
    const uint32_t ksb = fbase;
    const uint32_t vsb = fbase + F_K * 4;
    const uint32_t pwb = fbase + (2 * F_K + wid * F_PW) * 4;
    unsigned* pw = dyn_smem + 2 * F_K + wid * F_PW;

    const int lrow = (lane & 7) + ((lane >> 3) & 1) * 8;
    const int lcw = (lane >> 4) * 4;

    const size_t base = (size_t)b * SEQ * QKV_DIM;

    // Q fragments (fp16, scale*log2e folded)
    unsigned qa[2][4][4];
#pragma unroll
    for (int mt = 0; mt < 2; mt++) {
        const int row = qt * 128 + wid * 32 + mt * 16 + r0;
        const float* p = qkv + base + (size_t)row * QKV_DIM + h * HEAD_DIM;
        const float* p8 = p + (size_t)8 * QKV_DIM;
#pragma unroll
        for (int kc = 0; kc < 4; kc++) {
            float2 x0 = *(const float2*)(p + kc * 16 + 2 * q4);
            float2 x1 = *(const float2*)(p + kc * 16 + 2 * q4 + 8);
            float2 y0 = *(const float2*)(p8 + kc * 16 + 2 * q4);
            float2 y1 = *(const float2*)(p8 + kc * 16 + 2 * q4 + 8);
            qa[mt][kc][0] = h2pack(x0.x * QSCALE, x0.y * QSCALE);
            qa[mt][kc][1] = h2pack(y0.x * QSCALE, y0.y * QSCALE);
            qa[mt][kc][2] = h2pack(x1.x * QSCALE, x1.y * QSCALE);
            qa[mt][kc][3] = h2pack(y1.x * QSCALE, y1.y * QSCALE);
        }
    }

    float o[2][8][4];
#pragma unroll
    for (int mt = 0; mt < 2; mt++)
#pragma unroll
        for (int nc = 0; nc < 8; nc++)
#pragma unroll
            for (int e = 0; e < 4; e++) o[mt][nc][e] = 0.f;
    float mA[2] = {-1e30f, -1e30f}, mB[2] = {-1e30f, -1e30f};
    float lA[2] = {0.f, 0.f}, lB[2] = {0.f, 0.f};

    const int kkey = tid >> 1;             // key row 0..63
    const int koff = (tid & 1) * 32;       // 32-element half of the row

    for (int kt = 0; kt < SEQ / 64; kt++) {
        // ---- K/V tile fill (row-major fp16) ----
        {
            const float* kg = qkv + base + (size_t)(kt * 64 + kkey) * QKV_DIM
                              + DIM + h * HEAD_DIM + koff;
            const float* vg = kg + DIM;
            float kf[32], vf[32];
#pragma unroll
            for (int i = 0; i < 8; i++) {
                float4 t = *(const float4*)(kg + i * 4);
                kf[i * 4 + 0] = t.x; kf[i * 4 + 1] = t.y;
                kf[i * 4 + 2] = t.z; kf[i * 4 + 3] = t.w;
                float4 u = *(const float4*)(vg + i * 4);
                vf[i * 4 + 0] = u.x; vf[i * 4 + 1] = u.y;
                vf[i * 4 + 2] = u.z; vf[i * 4 + 3] = u.w;
            }
            unsigned kw[16], vw[16];
#pragma unroll
            for (int w = 0; w < 16; w++) {
                kw[w] = h2pack(kf[2 * w], kf[2 * w + 1]);
                vw[w] = h2pack(vf[2 * w], vf[2 * w + 1]);
            }
            unsigned* kd = dyn_smem + kkey * FS + koff / 2;
            unsigned* vd = dyn_smem + F_K + kkey * FS + koff / 2;
#pragma unroll
            for (int i = 0; i < 4; i++) {
                *(uint4*)&kd[i * 4] = make_uint4(kw[i * 4], kw[i * 4 + 1],
                                                 kw[i * 4 + 2], kw[i * 4 + 3]);
                *(uint4*)&vd[i * 4] = make_uint4(vw[i * 4], vw[i * 4 + 1],
                                                 vw[i * 4 + 2], vw[i * 4 + 3]);
            }
        }
        __syncthreads();

        // ---- S = Q*K^T (32x64 per warp, 4 k-steps) ----
        float sc[2][8][4];
#pragma unroll
        for (int nc = 0; nc < 8; nc++)
#pragma unroll
            for (int e = 0; e < 4; e++) { sc[0][nc][e] = 0.f; sc[1][nc][e] = 0.f; }
#pragma unroll
        for (int kc = 0; kc < 4; kc++) {
#pragma unroll
            for (int np = 0; np < 4; np++) {
                unsigned bf[4];
                ldsm4(bf, ksb + 4 * ((np * 16 + lrow) * FS + kc * 8 + lcw));
                mma_fp16(sc[0][2 * np], qa[0][kc], bf[0], bf[2]);
                mma_fp16(sc[1][2 * np], qa[1][kc], bf[0], bf[2]);
                mma_fp16(sc[0][2 * np + 1], qa[0][kc], bf[1], bf[3]);
                mma_fp16(sc[1][2 * np + 1], qa[1][kc], bf[1], bf[3]);
            }
        }

        // ---- online softmax (exp2 domain) + P store (fp16) ----
#pragma unroll
        for (int mt = 0; mt < 2; mt++) {
            float tA = -1e30f, tB = -1e30f;
#pragma unroll
            for (int nc = 0; nc < 8; nc++) {
                tA = fmaxf(tA, fmaxf(sc[mt][nc][0], sc[mt][nc][1]));
                tB = fmaxf(tB, fmaxf(sc[mt][nc][2], sc[mt][nc][3]));
            }
            tA = fmaxf(tA, __shfl_xor_sync(0xffffffffu, tA, 1));
            tA = fmaxf(tA, __shfl_xor_sync(0xffffffffu, tA, 2));
            tB = fmaxf(tB, __shfl_xor_sync(0xffffffffu, tB, 1));
            tB = fmaxf(tB, __shfl_xor_sync(0xffffffffu, tB, 2));
            const float mnA = fmaxf(mA[mt], tA);
            const float mnB = fmaxf(mB[mt], tB);
            const float cA = ex2(mA[mt] - mnA);
            const float cB = ex2(mB[mt] - mnB);
            mA[mt] = mnA; mB[mt] = mnB;
            lA[mt] *= cA; lB[mt] *= cB;
#pragma unroll
            for (int nc = 0; nc < 8; nc++) {
                o[mt][nc][0] *= cA; o[mt][nc][1] *= cA;
                o[mt][nc][2] *= cB; o[mt][nc][3] *= cB;
                const float p0 = ex2(sc[mt][nc][0] - mnA);
                const float p1 = ex2(sc[mt][nc][1] - mnA);
                const float p2 = ex2(sc[mt][nc][2] - mnB);
                const float p3 = ex2(sc[mt][nc][3] - mnB);
                lA[mt] += p0 + p1; lB[mt] += p2 + p3;
                pw[(mt * 16 + r0) * FS + nc * 4 + q4] = h2pack(p0, p1);
                pw[(mt * 16 + r0 + 8) * FS + nc * 4 + q4] = h2pack(p2, p3);
            }
        }
        __syncwarp();

        // ---- O += P*V (4 k-steps over 64 keys) ----
#pragma unroll
        for (int kb = 0; kb < 4; kb++) {
            unsigned af[2][4];
#pragma unroll
            for (int mt = 0; mt < 2; mt++)
                ldsm4(af[mt], pwb + 4 * ((mt * 16 + lrow) * FS + kb * 8 + lcw));
#pragma unroll
            for (int dp = 0; dp < 4; dp++) {
                unsigned bf[4];
                ldsm4t(bf, vsb + 4 * ((kb * 16 + lrow) * FS + dp * 8 + lcw));
                mma_fp16(o[0][2 * dp], af[0], bf[0], bf[1]);
                mma_fp16(o[1][2 * dp], af[1], bf[0], bf[1]);
                mma_fp16(o[0][2 * dp + 1], af[0], bf[2], bf[3]);
                mma_fp16(o[1][2 * dp + 1], af[1], bf[2], bf[3]);
            }
        }
        __syncthreads();
    }

    // ---- epilogue ----
#pragma unroll
    for (int mt = 0; mt < 2; mt++) {
        float la = lA[mt], lb = lB[mt];
        la += __shfl_xor_sync(0xffffffffu, la, 1);
        la += __shfl_xor_sync(0xffffffffu, la, 2);
        lb += __shfl_xor_sync(0xffffffffu, lb, 1);
        lb += __shfl_xor_sync(0xffffffffu, lb, 2);
        const float ia = 1.f / la, ib = 1.f / lb;
        const int row = qt * 128 + wid * 32 + mt * 16 + r0;
        float* oA = out + ((size_t)b * SEQ + row) * DIM + h * HEAD_DIM;
        float* oB = oA + (size_t)8 * DIM;
#pragma unroll
        for (int nc = 0; nc < 8; nc++) {
            const int col = nc * 8 + 2 * q4;
            *(float2*)(oA + col) = make_float2(o[mt][nc][0] * ia, o[mt][nc][1] * ia);
            *(float2*)(oB + col) = make_float2(o[mt][nc][2] * ib, o[mt][nc][3] * ib);
        }
    }
}

// ===========================================================================
extern "C" void kernel_launch(void* const* d_in, const int* in_sizes, int n_in,
                              void* d_out, int out_size) {
    const float* x      = (const float*)d_in[0];
    const float* w_qkv  = (const float*)d_in[1];
    const float* b_qkv  = (const float*)d_in[2];
    const float* w_proj = (const float*)d_in[3];
    const float* b_proj = (const float*)d_in[4];
    float* out = (float*)d_out;

    float* qkv = nullptr;
    float* att = nullptr;
    cudaGetSymbolAddress((void**)&qkv, g_qkv);
    cudaGetSymbolAddress((void**)&att, g_att);

    const int M = BATCH * SEQ;               // 8192
    const int FA_SMEM = F_WORDS * 4;         // 36864 B

    cudaFuncSetAttribute(gemm_fp16, cudaFuncAttributeMaxDynamicSharedMemorySize,
                         GEMM_SMEM_B);
    cudaFuncSetAttribute(flash_fp16, cudaFuncAttributeMaxDynamicSharedMemorySize,
                         FA_SMEM);

    {
        dim3 grid(QKV_DIM / 128, M / 128);   // (18, 64)
        gemm_fp16<<<grid, 128, GEMM_SMEM_B>>>(x, w_qkv, b_qkv, qkv, M, QKV_DIM, DIM);
    }
    {
        dim3 grid(SEQ / 128, HEADS, BATCH);  // (16, 12, 4)
        flash_fp16<<<grid, 128, FA_SMEM>>>(qkv, att);
    }
    {
        dim3 grid(DIM / 128, M / 128);       // (6, 64)
        gemm_fp16<<<grid, 128, GEMM_SMEM_B>>>(att, w_proj, b_proj, out, M, DIM, DIM);
    }
}

// round 12
// speedup vs baseline: 2.2272x; 1.6480x over previous
#include <cuda_runtime.h>
#include <cuda_fp16.h>
#include <math.h>
#include <cstdint>

#define DIM 768
#define HEADS 12
#define HEAD_DIM 64
#define BATCH 4
#define SEQ 2048
#define QKV_DIM (3 * DIM)
#define QSCALE 0.18033688011112042f  /* 0.125 * log2(e) */

__device__ __half g_qkv[(size_t)BATCH * SEQ * QKV_DIM];
__device__ __half g_att[(size_t)BATCH * SEQ * DIM];
__device__ __half g_xh[(size_t)BATCH * SEQ * DIM];
__device__ __half g_wqkv[(size_t)QKV_DIM * DIM];
__device__ __half g_wproj[(size_t)DIM * DIM];

__device__ __forceinline__ float ex2(float x) {
    float y;
    asm("ex2.approx.f32 %0, %1;" : "=f"(y) : "f"(x));
    return y;
}
__device__ __forceinline__ unsigned h2pack(float a, float b) {
    __half2 h = __floats2half2_rn(a, b);
    return *reinterpret_cast<unsigned*>(&h);
}
__device__ __forceinline__ uint32_t smem_u32(const void* p) {
    uint32_t a;
    asm("{ .reg .u64 t; cvta.to.shared.u64 t, %1; cvt.u32.u64 %0, t; }"
        : "=r"(a) : "l"(p));
    return a;
}
__device__ __forceinline__ void mma_fp16(float c[4], const unsigned a[4],
                                         unsigned b0, unsigned b1) {
    asm volatile(
        "mma.sync.aligned.m16n8k16.row.col.f32.f16.f16.f32 "
        "{%0,%1,%2,%3}, {%4,%5,%6,%7}, {%8,%9}, {%0,%1,%2,%3};"
        : "+f"(c[0]), "+f"(c[1]), "+f"(c[2]), "+f"(c[3])
        : "r"(a[0]), "r"(a[1]), "r"(a[2]), "r"(a[3]), "r"(b0), "r"(b1));
}
__device__ __forceinline__ void ldsm4(unsigned r[4], uint32_t addr) {
    asm volatile("ldmatrix.sync.aligned.m8n8.x4.shared.b16 {%0,%1,%2,%3}, [%4];"
                 : "=r"(r[0]), "=r"(r[1]), "=r"(r[2]), "=r"(r[3]) : "r"(addr));
}
__device__ __forceinline__ void ldsm4t(unsigned r[4], uint32_t addr) {
    asm volatile("ldmatrix.sync.aligned.m8n8.x4.trans.shared.b16 {%0,%1,%2,%3}, [%4];"
                 : "=r"(r[0]), "=r"(r[1]), "=r"(r[2]), "=r"(r[3]) : "r"(addr));
}

// ---------------------------------------------------------------------------
// fp32 -> fp16 conversion (grid-stride free, exact-size launch; n % 2048 == 0)
// ---------------------------------------------------------------------------
__global__ __launch_bounds__(256) void f2h(const float* __restrict__ in,
                                           __half* __restrict__ out) {
    const int i = (blockIdx.x * 256 + threadIdx.x) * 8;
    float4 v0 = *(const float4*)(in + i);
    float4 v1 = *(const float4*)(in + i + 4);
    uint4 o;
    o.x = h2pack(v0.x, v0.y); o.y = h2pack(v0.z, v0.w);
    o.z = h2pack(v1.x, v1.y); o.w = h2pack(v1.z, v1.w);
    *(uint4*)(out + i) = o;
}

// ===========================================================================
// FP16-in GEMM (NT): C[M,N] = A[M,K]*B[N,K]^T + bias (fp32 accum).
// A, B fp16; C fp16 (HALF_OUT=1, with QSCALE on cols < qcols) or fp32.
// 128x128 CTA tile, BK=16, 128 threads = 4 warps (2m x 2n), warp 64x64.
// Pure LDG->STS producer path (no conversion); double-buffered.
// ===========================================================================
#define GS 12
#define G_HALF (128 * GS)
#define G_BUF2 (2 * G_HALF)
#define GEMM_SMEM_B (2 * G_BUF2 * 4)  // 24576 B

extern __shared__ unsigned dyn_smem[];

template <int HALF_OUT>
__global__ __launch_bounds__(128) void gemm_h(
    const __half* __restrict__ A, const __half* __restrict__ B,
    const float* __restrict__ bias, void* __restrict__ Cv,
    int M, int N, int K, int qcols) {
    const int tid = threadIdx.x;
    const int lane = tid & 31;
    const int wid = tid >> 5;
    const int wm = wid & 1, wn = wid >> 1;
    const int bx = blockIdx.x, by = blockIdx.y;
    const int r0 = lane >> 2, q4 = lane & 3;
    const uint32_t sbase = smem_u32(dyn_smem);

    const int lrow = (lane & 7) + ((lane >> 3) & 1) * 8;
    const int lcw = (lane >> 4) * 4;

    const __half* Ag = A + (size_t)(by * 128 + tid) * K;
    const __half* Bg = B + (size_t)(bx * 128 + tid) * K;

    uint4 pa0, pa1, pb0, pb1;
    pa0 = *(const uint4*)Ag;       pa1 = *(const uint4*)(Ag + 8);
    pb0 = *(const uint4*)Bg;       pb1 = *(const uint4*)(Bg + 8);

    float acc[4][8][4];
#pragma unroll
    for (int i = 0; i < 4; i++)
#pragma unroll
        for (int j = 0; j < 8; j++)
#pragma unroll
            for (int e = 0; e < 4; e++) acc[i][j][e] = 0.f;

    auto store_tile = [&](unsigned* s) {
        unsigned* As = s;
        unsigned* Bs = s + G_HALF;
        *(uint4*)&As[tid * GS]     = pa0;
        *(uint4*)&As[tid * GS + 4] = pa1;
        *(uint4*)&Bs[tid * GS]     = pb0;
        *(uint4*)&Bs[tid * GS + 4] = pb1;
    };

    store_tile(dyn_smem);
    __syncthreads();

    const int NT = K / 16;
    for (int t = 0; t < NT; t++) {
        if (t + 1 < NT) {
            const __half* ap = Ag + (t + 1) * 16;
            const __half* bp = Bg + (t + 1) * 16;
            pa0 = *(const uint4*)ap;       pa1 = *(const uint4*)(ap + 8);
            pb0 = *(const uint4*)bp;       pb1 = *(const uint4*)(bp + 8);
        }
        {
            const uint32_t stg = sbase + (t & 1) * (G_BUF2 * 4);
            unsigned af[4][4];
#pragma unroll
            for (int mt = 0; mt < 4; mt++) {
                const int m0 = (wm * 4 + mt) * 16;
                ldsm4(af[mt], stg + 4 * ((m0 + lrow) * GS + lcw));
            }
#pragma unroll
            for (int np = 0; np < 4; np++) {
                const int n0 = wn * 64 + np * 16;
                unsigned bf[4];
                ldsm4(bf, stg + 4 * (G_HALF + (n0 + lrow) * GS + lcw));
#pragma unroll
                for (int mt = 0; mt < 4; mt++) {
                    mma_fp16(acc[mt][2 * np], af[mt], bf[0], bf[2]);
                    mma_fp16(acc[mt][2 * np + 1], af[mt], bf[1], bf[3]);
                }
            }
        }
        if (t + 1 < NT) store_tile(dyn_smem + ((t + 1) & 1) * G_BUF2);
        __syncthreads();
    }

    // epilogue
#pragma unroll
    for (int nc = 0; nc < 8; nc++) {
        const int col = bx * 128 + wn * 64 + nc * 8 + 2 * q4;
        const float bv0 = __ldg(&bias[col]);
        const float bv1 = __ldg(&bias[col + 1]);
        const float scl = (HALF_OUT && col < qcols) ? QSCALE : 1.f;
#pragma unroll
        for (int mt = 0; mt < 4; mt++) {
            const int row = by * 128 + wm * 64 + mt * 16 + r0;
            if (HALF_OUT) {
                __half* C = (__half*)Cv;
                *(unsigned*)&C[(size_t)row * N + col] =
                    h2pack((acc[mt][nc][0] + bv0) * scl, (acc[mt][nc][1] + bv1) * scl);
                *(unsigned*)&C[(size_t)(row + 8) * N + col] =
                    h2pack((acc[mt][nc][2] + bv0) * scl, (acc[mt][nc][3] + bv1) * scl);
            } else {
                float* C = (float*)Cv;
                *(float2*)&C[(size_t)row * N + col] =
                    make_float2(acc[mt][nc][0] + bv0, acc[mt][nc][1] + bv1);
                *(float2*)&C[(size_t)(row + 8) * N + col] =
                    make_float2(acc[mt][nc][2] + bv0, acc[mt][nc][3] + bv1);
            }
        }
    }
}

// ===========================================================================
// FP16 flash attention, fp16 qkv in / fp16 att out. Q pre-scaled by QSCALE
// (folded into QKV GEMM epilogue). Same fragment geometry as R9.
// ===========================================================================
#define FS 36
#define F_K (64 * FS)
#define F_PW (32 * FS)
#define F_WORDS (2 * F_K + 4 * F_PW)   // 9216 words = 36864 B

__global__ __launch_bounds__(128) void flash_h(
    const __half* __restrict__ qkv, __half* __restrict__ out) {
    const int tid = threadIdx.x;
    const int lane = tid & 31;
    const int wid = tid >> 5;
    const int r0 = lane >> 2, q4 = lane & 3;
    const int qt = blockIdx.x, h = blockIdx.y, b = blockIdx.z;
    const uint32_t fbase = smem_u32(dyn_smem);
    const uint32_t ksb = fbase;
    const uint32_t vsb = fbase + F_K * 4;
    const uint32_t pwb = fbase + (2 * F_K + wid * F_PW) * 4;
    unsigned* pw = dyn_smem + 2 * F_K + wid * F_PW;

    const int lrow = (lane & 7) + ((lane >> 3) & 1) * 8;
    const int lcw = (lane >> 4) * 4;

    const size_t base = (size_t)b * SEQ * QKV_DIM;

    // Q fragments: direct u32 (half2) loads; QSCALE already applied upstream
    unsigned qa[2][4][4];
#pragma unroll
    for (int mt = 0; mt < 2; mt++) {
        const int row = qt * 128 + wid * 32 + mt * 16 + r0;
        const __half* p = qkv + base + (size_t)row * QKV_DIM + h * HEAD_DIM;
        const __half* p8 = p + (size_t)8 * QKV_DIM;
#pragma unroll
        for (int kc = 0; kc < 4; kc++) {
            qa[mt][kc][0] = *(const unsigned*)(p + kc * 16 + 2 * q4);
            qa[mt][kc][1] = *(const unsigned*)(p8 + kc * 16 + 2 * q4);
            qa[mt][kc][2] = *(const unsigned*)(p + kc * 16 + 2 * q4 + 8);
            qa[mt][kc][3] = *(const unsigned*)(p8 + kc * 16 + 2 * q4 + 8);
        }
    }

    float o[2][8][4];
#pragma unroll
    for (int mt = 0; mt < 2; mt++)
#pragma unroll
        for (int nc = 0; nc < 8; nc++)
#pragma unroll
            for (int e = 0; e < 4; e++) o[mt][nc][e] = 0.f;
    float mA[2] = {-1e30f, -1e30f}, mB[2] = {-1e30f, -1e30f};
    float lA[2] = {0.f, 0.f}, lB[2] = {0.f, 0.f};

    const int kkey = tid >> 1;
    const int koff = (tid & 1) * 32;      // half-row offset in halves

    for (int kt = 0; kt < SEQ / 64; kt++) {
        // ---- K/V tile fill: straight uint4 copies ----
        {
            const __half* kg = qkv + base + (size_t)(kt * 64 + kkey) * QKV_DIM
                               + DIM + h * HEAD_DIM + koff;
            const __half* vg = kg + DIM;
            uint4 k0 = *(const uint4*)kg;
            uint4 k1 = *(const uint4*)(kg + 8);
            uint4 k2 = *(const uint4*)(kg + 16);
            uint4 k3 = *(const uint4*)(kg + 24);
            uint4 v0 = *(const uint4*)vg;
            uint4 v1 = *(const uint4*)(vg + 8);
            uint4 v2 = *(const uint4*)(vg + 16);
            uint4 v3 = *(const uint4*)(vg + 24);
            unsigned* kd = dyn_smem + kkey * FS + koff / 2;
            unsigned* vd = dyn_smem + F_K + kkey * FS + koff / 2;
            *(uint4*)&kd[0] = k0;  *(uint4*)&kd[4] = k1;
            *(uint4*)&kd[8] = k2;  *(uint4*)&kd[12] = k3;
            *(uint4*)&vd[0] = v0;  *(uint4*)&vd[4] = v1;
            *(uint4*)&vd[8] = v2;  *(uint4*)&vd[12] = v3;
        }
        __syncthreads();

        // ---- S = Q*K^T ----
        float sc[2][8][4];
#pragma unroll
        for (int nc = 0; nc < 8; nc++)
#pragma unroll
            for (int e = 0; e < 4; e++) { sc[0][nc][e] = 0.f; sc[1][nc][e] = 0.f; }
#pragma unroll
        for (int kc = 0; kc < 4; kc++) {
#pragma unroll
            for (int np = 0; np < 4; np++) {
                unsigned bf[4];
                ldsm4(bf, ksb + 4 * ((np * 16 + lrow) * FS + kc * 8 + lcw));
                mma_fp16(sc[0][2 * np], qa[0][kc], bf[0], bf[2]);
                mma_fp16(sc[1][2 * np], qa[1][kc], bf[0], bf[2]);
                mma_fp16(sc[0][2 * np + 1], qa[0][kc], bf[1], bf[3]);
                mma_fp16(sc[1][2 * np + 1], qa[1][kc], bf[1], bf[3]);
            }
        }

        // ---- online softmax (exp2 domain) + P store ----
#pragma unroll
        for (int mt = 0; mt < 2; mt++) {
            float tA = -1e30f, tB = -1e30f;
#pragma unroll
            for (int nc = 0; nc < 8; nc++) {
                tA = fmaxf(tA, fmaxf(sc[mt][nc][0], sc[mt][nc][1]));
                tB = fmaxf(tB, fmaxf(sc[mt][nc][2], sc[mt][nc][3]));
            }
            tA = fmaxf(tA, __shfl_xor_sync(0xffffffffu, tA, 1));
            tA = fmaxf(tA, __shfl_xor_sync(0xffffffffu, tA, 2));
            tB = fmaxf(tB, __shfl_xor_sync(0xffffffffu, tB, 1));
            tB = fmaxf(tB, __shfl_xor_sync(0xffffffffu, tB, 2));
            const float mnA = fmaxf(mA[mt], tA);
            const float mnB = fmaxf(mB[mt], tB);
            const float cA = ex2(mA[mt] - mnA);
            const float cB = ex2(mB[mt] - mnB);
            mA[mt] = mnA; mB[mt] = mnB;
            lA[mt] *= cA; lB[mt] *= cB;
#pragma unroll
            for (int nc = 0; nc < 8; nc++) {
                o[mt][nc][0] *= cA; o[mt][nc][1] *= cA;
                o[mt][nc][2] *= cB; o[mt][nc][3] *= cB;
                const float p0 = ex2(sc[mt][nc][0] - mnA);
                const float p1 = ex2(sc[mt][nc][1] - mnA);
                const float p2 = ex2(sc[mt][nc][2] - mnB);
                const float p3 = ex2(sc[mt][nc][3] - mnB);
                lA[mt] += p0 + p1; lB[mt] += p2 + p3;
                pw[(mt * 16 + r0) * FS + nc * 4 + q4] = h2pack(p0, p1);
                pw[(mt * 16 + r0 + 8) * FS + nc * 4 + q4] = h2pack(p2, p3);
            }
        }
        __syncwarp();

        // ---- O += P*V ----
#pragma unroll
        for (int kb = 0; kb < 4; kb++) {
            unsigned af[2][4];
#pragma unroll
            for (int mt = 0; mt < 2; mt++)
                ldsm4(af[mt], pwb + 4 * ((mt * 16 + lrow) * FS + kb * 8 + lcw));
#pragma unroll
            for (int dp = 0; dp < 4; dp++) {
                unsigned bf[4];
                ldsm4t(bf, vsb + 4 * ((kb * 16 + lrow) * FS + dp * 8 + lcw));
                mma_fp16(o[0][2 * dp], af[0], bf[0], bf[1]);
                mma_fp16(o[1][2 * dp], af[1], bf[0], bf[1]);
                mma_fp16(o[0][2 * dp + 1], af[0], bf[2], bf[3]);
                mma_fp16(o[1][2 * dp + 1], af[1], bf[2], bf[3]);
            }
        }
        __syncthreads();
    }

    // ---- epilogue: fp16 att out ----
#pragma unroll
    for (int mt = 0; mt < 2; mt++) {
        float la = lA[mt], lb = lB[mt];
        la += __shfl_xor_sync(0xffffffffu, la, 1);
        la += __shfl_xor_sync(0xffffffffu, la, 2);
        lb += __shfl_xor_sync(0xffffffffu, lb, 1);
        lb += __shfl_xor_sync(0xffffffffu, lb, 2);
        const float ia = 1.f / la, ib = 1.f / lb;
        const int row = qt * 128 + wid * 32 + mt * 16 + r0;
        __half* oA = out + ((size_t)b * SEQ + row) * DIM + h * HEAD_DIM;
        __half* oB = oA + (size_t)8 * DIM;
#pragma unroll
        for (int nc = 0; nc < 8; nc++) {
            const int col = nc * 8 + 2 * q4;
            *(unsigned*)(oA + col) = h2pack(o[mt][nc][0] * ia, o[mt][nc][1] * ia);
            *(unsigned*)(oB + col) = h2pack(o[mt][nc][2] * ib, o[mt][nc][3] * ib);
        }
    }
}

// ===========================================================================
extern "C" void kernel_launch(void* const* d_in, const int* in_sizes, int n_in,
                              void* d_out, int out_size) {
    const float* x      = (const float*)d_in[0];
    const float* w_qkv  = (const float*)d_in[1];
    const float* b_qkv  = (const float*)d_in[2];
    const float* w_proj = (const float*)d_in[3];
    const float* b_proj = (const float*)d_in[4];
    float* out = (float*)d_out;

    __half *qkv, *att, *xh, *wq, *wp;
    cudaGetSymbolAddress((void**)&qkv, g_qkv);
    cudaGetSymbolAddress((void**)&att, g_att);
    cudaGetSymbolAddress((void**)&xh, g_xh);
    cudaGetSymbolAddress((void**)&wq, g_wqkv);
    cudaGetSymbolAddress((void**)&wp, g_wproj);

    const int M = BATCH * SEQ;               // 8192
    const int FA_SMEM = F_WORDS * 4;         // 36864 B

    cudaFuncSetAttribute(gemm_h<1>, cudaFuncAttributeMaxDynamicSharedMemorySize,
                         GEMM_SMEM_B);
    cudaFuncSetAttribute(gemm_h<0>, cudaFuncAttributeMaxDynamicSharedMemorySize,
                         GEMM_SMEM_B);
    cudaFuncSetAttribute(flash_h, cudaFuncAttributeMaxDynamicSharedMemorySize,
                         FA_SMEM);

    // 0) fp32 -> fp16 conversions
    f2h<<<(M * DIM) / 2048, 256>>>(x, xh);
    f2h<<<(QKV_DIM * DIM) / 2048, 256>>>(w_qkv, wq);
    f2h<<<(DIM * DIM) / 2048, 256>>>(w_proj, wp);

    // 1) QKV projection (fp16 out, Q columns pre-scaled by QSCALE)
    {
        dim3 grid(QKV_DIM / 128, M / 128);   // (18, 64)
        gemm_h<1><<<grid, 128, GEMM_SMEM_B>>>(xh, wq, b_qkv, qkv,
                                              M, QKV_DIM, DIM, DIM);
    }
    // 2) Flash attention (fp16 in/out)
    {
        dim3 grid(SEQ / 128, HEADS, BATCH);  // (16, 12, 4)
        flash_h<<<grid, 128, FA_SMEM>>>(qkv, att);
    }
    // 3) Output projection (fp32 out)
    {
        dim3 grid(DIM / 128, M / 128);       // (6, 64)
        gemm_h<0><<<grid, 128, GEMM_SMEM_B>>>(att, wp, b_proj, out,
                                              M, DIM, DIM, 0);
    }
}

// round 13
// speedup vs baseline: 2.3019x; 1.0335x over previous
#include <cuda_runtime.h>
#include <cuda_fp16.h>
#include <math.h>
#include <cstdint>

#define DIM 768
#define HEADS 12
#define HEAD_DIM 64
#define BATCH 4
#define SEQ 2048
#define QKV_DIM (3 * DIM)
#define QSCALE 0.18033688011112042f  /* 0.125 * log2(e) */

__device__ __half g_qkv[(size_t)BATCH * SEQ * QKV_DIM];
__device__ __half g_att[(size_t)BATCH * SEQ * DIM];
__device__ __half g_xh[(size_t)BATCH * SEQ * DIM];
__device__ __half g_wqkv[(size_t)QKV_DIM * DIM];
__device__ __half g_wproj[(size_t)DIM * DIM];

__device__ __forceinline__ float ex2(float x) {
    float y;
    asm("ex2.approx.f32 %0, %1;" : "=f"(y) : "f"(x));
    return y;
}
__device__ __forceinline__ unsigned h2pack(float a, float b) {
    __half2 h = __floats2half2_rn(a, b);
    return *reinterpret_cast<unsigned*>(&h);
}
__device__ __forceinline__ uint32_t smem_u32(const void* p) {
    uint32_t a;
    asm("{ .reg .u64 t; cvta.to.shared.u64 t, %1; cvt.u32.u64 %0, t; }"
        : "=r"(a) : "l"(p));
    return a;
}
__device__ __forceinline__ void mma_fp16(float c[4], const unsigned a[4],
                                         unsigned b0, unsigned b1) {
    asm volatile(
        "mma.sync.aligned.m16n8k16.row.col.f32.f16.f16.f32 "
        "{%0,%1,%2,%3}, {%4,%5,%6,%7}, {%8,%9}, {%0,%1,%2,%3};"
        : "+f"(c[0]), "+f"(c[1]), "+f"(c[2]), "+f"(c[3])
        : "r"(a[0]), "r"(a[1]), "r"(a[2]), "r"(a[3]), "r"(b0), "r"(b1));
}
__device__ __forceinline__ void ldsm4(unsigned r[4], uint32_t addr) {
    asm volatile("ldmatrix.sync.aligned.m8n8.x4.shared.b16 {%0,%1,%2,%3}, [%4];"
                 : "=r"(r[0]), "=r"(r[1]), "=r"(r[2]), "=r"(r[3]) : "r"(addr));
}
__device__ __forceinline__ void ldsm4t(unsigned r[4], uint32_t addr) {
    asm volatile("ldmatrix.sync.aligned.m8n8.x4.trans.shared.b16 {%0,%1,%2,%3}, [%4];"
                 : "=r"(r[0]), "=r"(r[1]), "=r"(r[2]), "=r"(r[3]) : "r"(addr));
}
__device__ __forceinline__ void cp16(uint32_t dst, const void* src) {
    asm volatile("cp.async.cg.shared.global [%0], [%1], 16;" :: "r"(dst), "l"(src));
}
#define CP_COMMIT() asm volatile("cp.async.commit_group;" ::: "memory")
#define CP_WAIT(n)  asm volatile("cp.async.wait_group %0;" :: "n"(n) : "memory")

// ---------------------------------------------------------------------------
__global__ __launch_bounds__(256) void f2h(const float* __restrict__ in,
                                           __half* __restrict__ out) {
    const int i = (blockIdx.x * 256 + threadIdx.x) * 8;
    float4 v0 = *(const float4*)(in + i);
    float4 v1 = *(const float4*)(in + i + 4);
    uint4 o;
    o.x = h2pack(v0.x, v0.y); o.y = h2pack(v0.z, v0.w);
    o.z = h2pack(v1.x, v1.y); o.w = h2pack(v1.z, v1.w);
    *(uint4*)(out + i) = o;
}

// ===========================================================================
// FP16 GEMM (NT) with 3-stage cp.async pipeline.
// 128x128 CTA tile, BK=16, 128 threads = 4 warps (2m x 2n), warp 64x64.
// ===========================================================================
#define GS 12
#define G_HALF (128 * GS)          // words per matrix per stage
#define G_STGW (2 * G_HALF)        // 3072 words per stage
#define G_STGB (G_STGW * 4)        // 12288 B
#define GEMM_SMEM_B (3 * G_STGB)   // 36864 B

extern __shared__ unsigned dyn_smem[];

template <int HALF_OUT>
__global__ __launch_bounds__(128) void gemm_h(
    const __half* __restrict__ A, const __half* __restrict__ B,
    const float* __restrict__ bias, void* __restrict__ Cv,
    int M, int N, int K, int qcols) {
    const int tid = threadIdx.x;
    const int lane = tid & 31;
    const int wid = tid >> 5;
    const int wm = wid & 1, wn = wid >> 1;
    const int bx = blockIdx.x, by = blockIdx.y;
    const int r0 = lane >> 2, q4 = lane & 3;
    const uint32_t sbase = smem_u32(dyn_smem);

    const int lrow = (lane & 7) + ((lane >> 3) & 1) * 8;
    const int lcw = (lane >> 4) * 4;

    const __half* Ag = A + (size_t)(by * 128 + tid) * K;
    const __half* Bg = B + (size_t)(bx * 128 + tid) * K;
    const uint32_t adst = tid * (GS * 4);           // byte offset within stage
    const uint32_t bdst = adst + G_HALF * 4;

    // precomputed ldmatrix offsets (stage-relative, bytes)
    uint32_t aoff[4], boff[4];
#pragma unroll
    for (int mt = 0; mt < 4; mt++)
        aoff[mt] = 4 * (((wm * 4 + mt) * 16 + lrow) * GS + lcw);
#pragma unroll
    for (int np = 0; np < 4; np++)
        boff[np] = 4 * (G_HALF + (wn * 64 + np * 16 + lrow) * GS + lcw);

    auto issue = [&](int s, int t) {
        const uint32_t stg = sbase + s * G_STGB;
        const __half* ap = Ag + t * 16;
        const __half* bp = Bg + t * 16;
        cp16(stg + adst, ap);
        cp16(stg + adst + 16, ap + 8);
        cp16(stg + bdst, bp);
        cp16(stg + bdst + 16, bp + 8);
    };

    float acc[4][8][4];
#pragma unroll
    for (int i = 0; i < 4; i++)
#pragma unroll
        for (int j = 0; j < 8; j++)
#pragma unroll
            for (int e = 0; e < 4; e++) acc[i][j][e] = 0.f;

    const int NT = K / 16;
    issue(0, 0); CP_COMMIT();
    issue(1, 1); CP_COMMIT();

    int s = 0, s2 = 2;
    for (int t = 0; t < NT; t++) {
        if (t == NT - 1) { CP_WAIT(0); } else { CP_WAIT(1); }
        __syncthreads();
        if (t + 2 < NT) {
            issue(s2, t + 2); CP_COMMIT();
        }
        const uint32_t stg = sbase + s * G_STGB;
        unsigned af[4][4];
#pragma unroll
        for (int mt = 0; mt < 4; mt++) ldsm4(af[mt], stg + aoff[mt]);
#pragma unroll
        for (int np = 0; np < 4; np++) {
            unsigned bf[4];
            ldsm4(bf, stg + boff[np]);
#pragma unroll
            for (int mt = 0; mt < 4; mt++) {
                mma_fp16(acc[mt][2 * np], af[mt], bf[0], bf[2]);
                mma_fp16(acc[mt][2 * np + 1], af[mt], bf[1], bf[3]);
            }
        }
        s = (s == 2) ? 0 : s + 1;
        s2 = (s2 == 2) ? 0 : s2 + 1;
    }

    // epilogue
#pragma unroll
    for (int nc = 0; nc < 8; nc++) {
        const int col = bx * 128 + wn * 64 + nc * 8 + 2 * q4;
        const float bv0 = __ldg(&bias[col]);
        const float bv1 = __ldg(&bias[col + 1]);
        const float scl = (HALF_OUT && col < qcols) ? QSCALE : 1.f;
#pragma unroll
        for (int mt = 0; mt < 4; mt++) {
            const int row = by * 128 + wm * 64 + mt * 16 + r0;
            if (HALF_OUT) {
                __half* C = (__half*)Cv;
                *(unsigned*)&C[(size_t)row * N + col] =
                    h2pack((acc[mt][nc][0] + bv0) * scl, (acc[mt][nc][1] + bv1) * scl);
                *(unsigned*)&C[(size_t)(row + 8) * N + col] =
                    h2pack((acc[mt][nc][2] + bv0) * scl, (acc[mt][nc][3] + bv1) * scl);
            } else {
                float* C = (float*)Cv;
                *(float2*)&C[(size_t)row * N + col] =
                    make_float2(acc[mt][nc][0] + bv0, acc[mt][nc][1] + bv1);
                *(float2*)&C[(size_t)(row + 8) * N + col] =
                    make_float2(acc[mt][nc][2] + bv0, acc[mt][nc][3] + bv1);
            }
        }
    }
}

// ===========================================================================
// FP16 flash attention with 2-stage cp.async K/V pipeline.
// CTA = 128 threads (4 warps), 128 q-rows, KV tile 64 keys. 1 sync per tile.
// ===========================================================================
#define FS 36
#define F_K (64 * FS)                    // 2304 words (one matrix)
#define F_STGW (2 * F_K)                 // K+V per stage, words
#define F_STGB (F_STGW * 4)              // 18432 B
#define F_PW (32 * FS)
#define FA_SMEM_B (2 * F_STGB + 4 * F_PW * 4)  // 55296 B

__global__ __launch_bounds__(128) void flash_h(
    const __half* __restrict__ qkv, __half* __restrict__ out) {
    const int tid = threadIdx.x;
    const int lane = tid & 31;
    const int wid = tid >> 5;
    const int r0 = lane >> 2, q4 = lane & 3;
    const int qt = blockIdx.x, h = blockIdx.y, b = blockIdx.z;
    const uint32_t fbase = smem_u32(dyn_smem);
    const uint32_t pwb = fbase + 2 * F_STGB + wid * (F_PW * 4);
    unsigned* pw = dyn_smem + 2 * F_STGW + wid * F_PW;

    const int lrow = (lane & 7) + ((lane >> 3) & 1) * 8;
    const int lcw = (lane >> 4) * 4;

    const size_t base = (size_t)b * SEQ * QKV_DIM;

    const int kkey = tid >> 1;
    const int koff = (tid & 1) * 32;
    const uint32_t kdst = kkey * (FS * 4) + koff * 2;   // byte offset in stage

    auto issue_kv = [&](int s, int kt) {
        const __half* kg = qkv + base + (size_t)(kt * 64 + kkey) * QKV_DIM
                           + DIM + h * HEAD_DIM + koff;
        const __half* vg = kg + DIM;
        const uint32_t stg = fbase + s * F_STGB;
#pragma unroll
        for (int i = 0; i < 4; i++) {
            cp16(stg + kdst + i * 16, kg + i * 8);
            cp16(stg + F_K * 4 + kdst + i * 16, vg + i * 8);
        }
    };

    // Q fragments (pre-scaled upstream)
    unsigned qa[2][4][4];
#pragma unroll
    for (int mt = 0; mt < 2; mt++) {
        const int row = qt * 128 + wid * 32 + mt * 16 + r0;
        const __half* p = qkv + base + (size_t)row * QKV_DIM + h * HEAD_DIM;
        const __half* p8 = p + (size_t)8 * QKV_DIM;
#pragma unroll
        for (int kc = 0; kc < 4; kc++) {
            qa[mt][kc][0] = *(const unsigned*)(p + kc * 16 + 2 * q4);
            qa[mt][kc][1] = *(const unsigned*)(p8 + kc * 16 + 2 * q4);
            qa[mt][kc][2] = *(const unsigned*)(p + kc * 16 + 2 * q4 + 8);
            qa[mt][kc][3] = *(const unsigned*)(p8 + kc * 16 + 2 * q4 + 8);
        }
    }

    float o[2][8][4];
#pragma unroll
    for (int mt = 0; mt < 2; mt++)
#pragma unroll
        for (int nc = 0; nc < 8; nc++)
#pragma unroll
            for (int e = 0; e < 4; e++) o[mt][nc][e] = 0.f;
    float mA[2] = {-1e30f, -1e30f}, mB[2] = {-1e30f, -1e30f};
    float lA[2] = {0.f, 0.f}, lB[2] = {0.f, 0.f};

    const int NT = SEQ / 64;
    issue_kv(0, 0); CP_COMMIT();

    for (int kt = 0; kt < NT; kt++) {
        CP_WAIT(0);
        __syncthreads();
        if (kt + 1 < NT) { issue_kv((kt + 1) & 1, kt + 1); CP_COMMIT(); }

        const uint32_t ksb = fbase + (kt & 1) * F_STGB;
        const uint32_t vsb = ksb + F_K * 4;

        // ---- S = Q*K^T ----
        float sc[2][8][4];
#pragma unroll
        for (int nc = 0; nc < 8; nc++)
#pragma unroll
            for (int e = 0; e < 4; e++) { sc[0][nc][e] = 0.f; sc[1][nc][e] = 0.f; }
#pragma unroll
        for (int kc = 0; kc < 4; kc++) {
#pragma unroll
            for (int np = 0; np < 4; np++) {
                unsigned bf[4];
                ldsm4(bf, ksb + 4 * ((np * 16 + lrow) * FS + kc * 8 + lcw));
                mma_fp16(sc[0][2 * np], qa[0][kc], bf[0], bf[2]);
                mma_fp16(sc[1][2 * np], qa[1][kc], bf[0], bf[2]);
                mma_fp16(sc[0][2 * np + 1], qa[0][kc], bf[1], bf[3]);
                mma_fp16(sc[1][2 * np + 1], qa[1][kc], bf[1], bf[3]);
            }
        }

        // ---- online softmax (exp2 domain) + P store ----
#pragma unroll
        for (int mt = 0; mt < 2; mt++) {
            float tA = -1e30f, tB = -1e30f;
#pragma unroll
            for (int nc = 0; nc < 8; nc++) {
                tA = fmaxf(tA, fmaxf(sc[mt][nc][0], sc[mt][nc][1]));
                tB = fmaxf(tB, fmaxf(sc[mt][nc][2], sc[mt][nc][3]));
            }
            tA = fmaxf(tA, __shfl_xor_sync(0xffffffffu, tA, 1));
            tA = fmaxf(tA, __shfl_xor_sync(0xffffffffu, tA, 2));
            tB = fmaxf(tB, __shfl_xor_sync(0xffffffffu, tB, 1));
            tB = fmaxf(tB, __shfl_xor_sync(0xffffffffu, tB, 2));
            const float mnA = fmaxf(mA[mt], tA);
            const float mnB = fmaxf(mB[mt], tB);
            const float cA = ex2(mA[mt] - mnA);
            const float cB = ex2(mB[mt] - mnB);
            mA[mt] = mnA; mB[mt] = mnB;
            lA[mt] *= cA; lB[mt] *= cB;
#pragma unroll
            for (int nc = 0; nc < 8; nc++) {
                o[mt][nc][0] *= cA; o[mt][nc][1] *= cA;
                o[mt][nc][2] *= cB; o[mt][nc][3] *= cB;
                const float p0 = ex2(sc[mt][nc][0] - mnA);
                const float p1 = ex2(sc[mt][nc][1] - mnA);
                const float p2 = ex2(sc[mt][nc][2] - mnB);
                const float p3 = ex2(sc[mt][nc][3] - mnB);
                lA[mt] += p0 + p1; lB[mt] += p2 + p3;
                pw[(mt * 16 + r0) * FS + nc * 4 + q4] = h2pack(p0, p1);
                pw[(mt * 16 + r0 + 8) * FS + nc * 4 + q4] = h2pack(p2, p3);
            }
        }
        __syncwarp();

        // ---- O += P*V ----
#pragma unroll
        for (int kb = 0; kb < 4; kb++) {
            unsigned af[2][4];
#pragma unroll
            for (int mt = 0; mt < 2; mt++)
                ldsm4(af[mt], pwb + 4 * ((mt * 16 + lrow) * FS + kb * 8 + lcw));
#pragma unroll
            for (int dp = 0; dp < 4; dp++) {
                unsigned bf[4];
                ldsm4t(bf, vsb + 4 * ((kb * 16 + lrow) * FS + dp * 8 + lcw));
                mma_fp16(o[0][2 * dp], af[0], bf[0], bf[1]);
                mma_fp16(o[1][2 * dp], af[1], bf[0], bf[1]);
                mma_fp16(o[0][2 * dp + 1], af[0], bf[2], bf[3]);
                mma_fp16(o[1][2 * dp + 1], af[1], bf[2], bf[3]);
            }
        }
    }

    // ---- epilogue ----
#pragma unroll
    for (int mt = 0; mt < 2; mt++) {
        float la = lA[mt], lb = lB[mt];
        la += __shfl_xor_sync(0xffffffffu, la, 1);
        la += __shfl_xor_sync(0xffffffffu, la, 2);
        lb += __shfl_xor_sync(0xffffffffu, lb, 1);
        lb += __shfl_xor_sync(0xffffffffu, lb, 2);
        const float ia = 1.f / la, ib = 1.f / lb;
        const int row = qt * 128 + wid * 32 + mt * 16 + r0;
        __half* oA = out + ((size_t)b * SEQ + row) * DIM + h * HEAD_DIM;
        __half* oB = oA + (size_t)8 * DIM;
#pragma unroll
        for (int nc = 0; nc < 8; nc++) {
            const int col = nc * 8 + 2 * q4;
            *(unsigned*)(oA + col) = h2pack(o[mt][nc][0] * ia, o[mt][nc][1] * ia);
            *(unsigned*)(oB + col) = h2pack(o[mt][nc][2] * ib, o[mt][nc][3] * ib);
        }
    }
}

// ===========================================================================
extern "C" void kernel_launch(void* const* d_in, const int* in_sizes, int n_in,
                              void* d_out, int out_size) {
    const float* x      = (const float*)d_in[0];
    const float* w_qkv  = (const float*)d_in[1];
    const float* b_qkv  = (const float*)d_in[2];
    const float* w_proj = (const float*)d_in[3];
    const float* b_proj = (const float*)d_in[4];
    float* out = (float*)d_out;

    __half *qkv, *att, *xh, *wq, *wp;
    cudaGetSymbolAddress((void**)&qkv, g_qkv);
    cudaGetSymbolAddress((void**)&att, g_att);
    cudaGetSymbolAddress((void**)&xh, g_xh);
    cudaGetSymbolAddress((void**)&wq, g_wqkv);
    cudaGetSymbolAddress((void**)&wp, g_wproj);

    const int M = BATCH * SEQ;               // 8192

    cudaFuncSetAttribute(gemm_h<1>, cudaFuncAttributeMaxDynamicSharedMemorySize,
                         GEMM_SMEM_B);
    cudaFuncSetAttribute(gemm_h<0>, cudaFuncAttributeMaxDynamicSharedMemorySize,
                         GEMM_SMEM_B);
    cudaFuncSetAttribute(flash_h, cudaFuncAttributeMaxDynamicSharedMemorySize,
                         FA_SMEM_B);

    f2h<<<(M * DIM) / 2048, 256>>>(x, xh);
    f2h<<<(QKV_DIM * DIM) / 2048, 256>>>(w_qkv, wq);
    f2h<<<(DIM * DIM) / 2048, 256>>>(w_proj, wp);

    {
        dim3 grid(QKV_DIM / 128, M / 128);   // (18, 64)
        gemm_h<1><<<grid, 128, GEMM_SMEM_B>>>(xh, wq, b_qkv, qkv,
                                              M, QKV_DIM, DIM, DIM);
    }
    {
        dim3 grid(SEQ / 128, HEADS, BATCH);  // (16, 12, 4)
        flash_h<<<grid, 128, FA_SMEM_B>>>(qkv, att);
    }
    {
        dim3 grid(DIM / 128, M / 128);       // (6, 64)
        gemm_h<0><<<grid, 128, GEMM_SMEM_B>>>(att, wp, b_proj, out,
                                              M, DIM, DIM, 0);
    }
}

// round 15
// speedup vs baseline: 2.3029x; 1.0004x over previous
#include <cuda_runtime.h>
#include <cuda_fp16.h>
#include <math.h>
#include <cstdint>

#define DIM 768
#define HEADS 12
#define HEAD_DIM 64
#define BATCH 4
#define SEQ 2048
#define QKV_DIM (3 * DIM)
#define QSCALE 0.18033688011112042f  /* 0.125 * log2(e) */

__device__ __half g_qkv[(size_t)BATCH * SEQ * QKV_DIM];
__device__ __half g_att[(size_t)BATCH * SEQ * DIM];
__device__ __half g_xh[(size_t)BATCH * SEQ * DIM];
__device__ __half g_wqkv[(size_t)QKV_DIM * DIM];
__device__ __half g_wproj[(size_t)DIM * DIM];

__device__ __forceinline__ float ex2(float x) {
    float y;
    asm("ex2.approx.f32 %0, %1;" : "=f"(y) : "f"(x));
    return y;
}
__device__ __forceinline__ unsigned h2pack(float a, float b) {
    __half2 h = __floats2half2_rn(a, b);
    return *reinterpret_cast<unsigned*>(&h);
}
__device__ __forceinline__ uint32_t smem_u32(const void* p) {
    uint32_t a;
    asm("{ .reg .u64 t; cvta.to.shared.u64 t, %1; cvt.u32.u64 %0, t; }"
        : "=r"(a) : "l"(p));
    return a;
}
__device__ __forceinline__ void mma_fp16(float c[4], const unsigned a[4],
                                         unsigned b0, unsigned b1) {
    asm volatile(
        "mma.sync.aligned.m16n8k16.row.col.f32.f16.f16.f32 "
        "{%0,%1,%2,%3}, {%4,%5,%6,%7}, {%8,%9}, {%0,%1,%2,%3};"
        : "+f"(c[0]), "+f"(c[1]), "+f"(c[2]), "+f"(c[3])
        : "r"(a[0]), "r"(a[1]), "r"(a[2]), "r"(a[3]), "r"(b0), "r"(b1));
}
__device__ __forceinline__ void ldsm4(unsigned r[4], uint32_t addr) {
    asm volatile("ldmatrix.sync.aligned.m8n8.x4.shared.b16 {%0,%1,%2,%3}, [%4];"
                 : "=r"(r[0]), "=r"(r[1]), "=r"(r[2]), "=r"(r[3]) : "r"(addr));
}
__device__ __forceinline__ void ldsm4t(unsigned r[4], uint32_t addr) {
    asm volatile("ldmatrix.sync.aligned.m8n8.x4.trans.shared.b16 {%0,%1,%2,%3}, [%4];"
                 : "=r"(r[0]), "=r"(r[1]), "=r"(r[2]), "=r"(r[3]) : "r"(addr));
}
__device__ __forceinline__ void cp16(uint32_t dst, const void* src) {
    asm volatile("cp.async.cg.shared.global [%0], [%1], 16;" :: "r"(dst), "l"(src));
}
#define CP_COMMIT() asm volatile("cp.async.commit_group;" ::: "memory")
#define CP_WAIT(n)  asm volatile("cp.async.wait_group %0;" :: "n"(n) : "memory")

// ---------------------------------------------------------------------------
__global__ __launch_bounds__(256) void f2h(const float* __restrict__ in,
                                           __half* __restrict__ out) {
    const int i = (blockIdx.x * 256 + threadIdx.x) * 8;
    float4 v0 = *(const float4*)(in + i);
    float4 v1 = *(const float4*)(in + i + 4);
    uint4 o;
    o.x = h2pack(v0.x, v0.y); o.y = h2pack(v0.z, v0.w);
    o.z = h2pack(v1.x, v1.y); o.w = h2pack(v1.z, v1.w);
    *(uint4*)(out + i) = o;
}

// ===========================================================================
// FP16 GEMM (NT), BK=32, 3-stage cp.async pipeline.
// 128x128 CTA tile, 128 threads = 4 warps (2m x 2n), warp 64x64.
// Stage: A 128x32 + B 128x32 halves, row stride 20 words (16 data + 4 pad).
// ===========================================================================
#define GRS 20                       // row stride (words)
#define G_HALFW (128 * GRS)          // 2560 words per matrix per stage
#define G_STGW (2 * G_HALFW)         // 5120 words per stage
#define G_STGB (G_STGW * 4)          // 20480 B
#define GEMM_SMEM_B (3 * G_STGB)     // 61440 B

extern __shared__ unsigned dyn_smem[];

template <int HALF_OUT>
__global__ __launch_bounds__(128) void gemm_h(
    const __half* __restrict__ A, const __half* __restrict__ B,
    const float* __restrict__ bias, void* __restrict__ Cv,
    int M, int N, int K, int qcols) {
    const int tid = threadIdx.x;
    const int lane = tid & 31;
    const int wid = tid >> 5;
    const int wm = wid & 1, wn = wid >> 1;
    const int bx = blockIdx.x, by = blockIdx.y;
    const int r0 = lane >> 2, q4 = lane & 3;
    const uint32_t sbase = smem_u32(dyn_smem);

    const int lrow = (lane & 7) + ((lane >> 3) & 1) * 8;
    const int lcw = (lane >> 4) * 4;

    const __half* Ag = A + (size_t)(by * 128 + tid) * K;
    const __half* Bg = B + (size_t)(bx * 128 + tid) * K;
    const uint32_t adst = tid * (GRS * 4);          // byte offset within stage
    const uint32_t bdst = adst + G_HALFW * 4;

    uint32_t aoff[4], boff[4];
#pragma unroll
    for (int mt = 0; mt < 4; mt++)
        aoff[mt] = 4 * (((wm * 4 + mt) * 16 + lrow) * GRS + lcw);
#pragma unroll
    for (int np = 0; np < 4; np++)
        boff[np] = 4 * (G_HALFW + (wn * 64 + np * 16 + lrow) * GRS + lcw);

    auto issue = [&](int s, int t) {
        const uint32_t stg = sbase + s * G_STGB;
        const __half* ap = Ag + t * 32;
        const __half* bp = Bg + t * 32;
#pragma unroll
        for (int i = 0; i < 4; i++) {
            cp16(stg + adst + i * 16, ap + i * 8);
            cp16(stg + bdst + i * 16, bp + i * 8);
        }
    };

    float acc[4][8][4];
#pragma unroll
    for (int i = 0; i < 4; i++)
#pragma unroll
        for (int j = 0; j < 8; j++)
#pragma unroll
            for (int e = 0; e < 4; e++) acc[i][j][e] = 0.f;

    const int NT = K / 32;   // 24
    issue(0, 0); CP_COMMIT();
    issue(1, 1); CP_COMMIT();

    int s = 0, s2 = 2;
    for (int t = 0; t < NT; t++) {
        if (t == NT - 1) { CP_WAIT(0); } else { CP_WAIT(1); }
        __syncthreads();
        if (t + 2 < NT) { issue(s2, t + 2); CP_COMMIT(); }
        const uint32_t stg = sbase + s * G_STGB;
#pragma unroll
        for (int kc = 0; kc < 2; kc++) {
            const uint32_t ko = kc * 32;   // 8 words
            unsigned af[4][4];
#pragma unroll
            for (int mt = 0; mt < 4; mt++) ldsm4(af[mt], stg + aoff[mt] + ko);
#pragma unroll
            for (int np = 0; np < 4; np++) {
                unsigned bf[4];
                ldsm4(bf, stg + boff[np] + ko);
#pragma unroll
                for (int mt = 0; mt < 4; mt++) {
                    mma_fp16(acc[mt][2 * np], af[mt], bf[0], bf[2]);
                    mma_fp16(acc[mt][2 * np + 1], af[mt], bf[1], bf[3]);
                }
            }
        }
        s = (s == 2) ? 0 : s + 1;
        s2 = (s2 == 2) ? 0 : s2 + 1;
    }

    // epilogue
#pragma unroll
    for (int nc = 0; nc < 8; nc++) {
        const int col = bx * 128 + wn * 64 + nc * 8 + 2 * q4;
        const float bv0 = __ldg(&bias[col]);
        const float bv1 = __ldg(&bias[col + 1]);
        const float scl = (HALF_OUT && col < qcols) ? QSCALE : 1.f;
#pragma unroll
        for (int mt = 0; mt < 4; mt++) {
            const int row = by * 128 + wm * 64 + mt * 16 + r0;
            if (HALF_OUT) {
                __half* C = (__half*)Cv;
                *(unsigned*)&C[(size_t)row * N + col] =
                    h2pack((acc[mt][nc][0] + bv0) * scl, (acc[mt][nc][1] + bv1) * scl);
                *(unsigned*)&C[(size_t)(row + 8) * N + col] =
                    h2pack((acc[mt][nc][2] + bv0) * scl, (acc[mt][nc][3] + bv1) * scl);
            } else {
                float* C = (float*)Cv;
                *(float2*)&C[(size_t)row * N + col] =
                    make_float2(acc[mt][nc][0] + bv0, acc[mt][nc][1] + bv1);
                *(float2*)&C[(size_t)(row + 8) * N + col] =
                    make_float2(acc[mt][nc][2] + bv0, acc[mt][nc][3] + bv1);
            }
        }
    }
}

// ===========================================================================
// FP16 flash attention, cp.async 2-stage K/V, P kept in registers:
// the S-matrix C-fragment layout equals the PV A-fragment layout, so P is
// repacked reg->reg (h2pack) with NO smem round trip.
// ===========================================================================
#define FS 36
#define F_K (64 * FS)                    // 2304 words (one matrix)
#define F_STGW (2 * F_K)                 // K+V per stage
#define F_STGB (F_STGW * 4)              // 18432 B
#define FA_SMEM_B (2 * F_STGB)           // 36864 B

__global__ __launch_bounds__(128) void flash_h(
    const __half* __restrict__ qkv, __half* __restrict__ out) {
    const int tid = threadIdx.x;
    const int lane = tid & 31;
    const int wid = tid >> 5;
    const int r0 = lane >> 2, q4 = lane & 3;
    const int qt = blockIdx.x, h = blockIdx.y, b = blockIdx.z;
    const uint32_t fbase = smem_u32(dyn_smem);

    const int lrow = (lane & 7) + ((lane >> 3) & 1) * 8;
    const int lcw = (lane >> 4) * 4;

    const size_t base = (size_t)b * SEQ * QKV_DIM;

    const int kkey = tid >> 1;
    const int koff = (tid & 1) * 32;
    const uint32_t kdst = kkey * (FS * 4) + koff * 2;

    auto issue_kv = [&](int s, int kt) {
        const __half* kg = qkv + base + (size_t)(kt * 64 + kkey) * QKV_DIM
                           + DIM + h * HEAD_DIM + koff;
        const __half* vg = kg + DIM;
        const uint32_t stg = fbase + s * F_STGB;
#pragma unroll
        for (int i = 0; i < 4; i++) {
            cp16(stg + kdst + i * 16, kg + i * 8);
            cp16(stg + F_K * 4 + kdst + i * 16, vg + i * 8);
        }
    };

    // Q fragments (pre-scaled upstream)
    unsigned qa[2][4][4];
#pragma unroll
    for (int mt = 0; mt < 2; mt++) {
        const int row = qt * 128 + wid * 32 + mt * 16 + r0;
        const __half* p = qkv + base + (size_t)row * QKV_DIM + h * HEAD_DIM;
        const __half* p8 = p + (size_t)8 * QKV_DIM;
#pragma unroll
        for (int kc = 0; kc < 4; kc++) {
            qa[mt][kc][0] = *(const unsigned*)(p + kc * 16 + 2 * q4);
            qa[mt][kc][1] = *(const unsigned*)(p8 + kc * 16 + 2 * q4);
            qa[mt][kc][2] = *(const unsigned*)(p + kc * 16 + 2 * q4 + 8);
            qa[mt][kc][3] = *(const unsigned*)(p8 + kc * 16 + 2 * q4 + 8);
        }
    }

    float o[2][8][4];
#pragma unroll
    for (int mt = 0; mt < 2; mt++)
#pragma unroll
        for (int nc = 0; nc < 8; nc++)
#pragma unroll
            for (int e = 0; e < 4; e++) o[mt][nc][e] = 0.f;
    float mA[2] = {-1e30f, -1e30f}, mB[2] = {-1e30f, -1e30f};
    float lA[2] = {0.f, 0.f}, lB[2] = {0.f, 0.f};

    const int NT = SEQ / 64;
    issue_kv(0, 0); CP_COMMIT();

    for (int kt = 0; kt < NT; kt++) {
        CP_WAIT(0);
        __syncthreads();
        if (kt + 1 < NT) { issue_kv((kt + 1) & 1, kt + 1); CP_COMMIT(); }

        const uint32_t ksb = fbase + (kt & 1) * F_STGB;
        const uint32_t vsb = ksb + F_K * 4;

        // ---- S = Q*K^T ----
        float sc[2][8][4];
#pragma unroll
        for (int nc = 0; nc < 8; nc++)
#pragma unroll
            for (int e = 0; e < 4; e++) { sc[0][nc][e] = 0.f; sc[1][nc][e] = 0.f; }
#pragma unroll
        for (int kc = 0; kc < 4; kc++) {
#pragma unroll
            for (int np = 0; np < 4; np++) {
                unsigned bf[4];
                ldsm4(bf, ksb + 4 * ((np * 16 + lrow) * FS + kc * 8 + lcw));
                mma_fp16(sc[0][2 * np], qa[0][kc], bf[0], bf[2]);
                mma_fp16(sc[1][2 * np], qa[1][kc], bf[0], bf[2]);
                mma_fp16(sc[0][2 * np + 1], qa[0][kc], bf[1], bf[3]);
                mma_fp16(sc[1][2 * np + 1], qa[1][kc], bf[1], bf[3]);
            }
        }

        // ---- online softmax (exp2 domain), P packed into registers ----
        unsigned pp[2][8][2];
#pragma unroll
        for (int mt = 0; mt < 2; mt++) {
            float tA = -1e30f, tB = -1e30f;
#pragma unroll
            for (int nc = 0; nc < 8; nc++) {
                tA = fmaxf(tA, fmaxf(sc[mt][nc][0], sc[mt][nc][1]));
                tB = fmaxf(tB, fmaxf(sc[mt][nc][2], sc[mt][nc][3]));
            }
            tA = fmaxf(tA, __shfl_xor_sync(0xffffffffu, tA, 1));
            tA = fmaxf(tA, __shfl_xor_sync(0xffffffffu, tA, 2));
            tB = fmaxf(tB, __shfl_xor_sync(0xffffffffu, tB, 1));
            tB = fmaxf(tB, __shfl_xor_sync(0xffffffffu, tB, 2));
            const float mnA = fmaxf(mA[mt], tA);
            const float mnB = fmaxf(mB[mt], tB);
            const float cA = ex2(mA[mt] - mnA);
            const float cB = ex2(mB[mt] - mnB);
            mA[mt] = mnA; mB[mt] = mnB;
            lA[mt] *= cA; lB[mt] *= cB;
#pragma unroll
            for (int nc = 0; nc < 8; nc++) {
                o[mt][nc][0] *= cA; o[mt][nc][1] *= cA;
                o[mt][nc][2] *= cB; o[mt][nc][3] *= cB;
                const float p0 = ex2(sc[mt][nc][0] - mnA);
                const float p1 = ex2(sc[mt][nc][1] - mnA);
                const float p2 = ex2(sc[mt][nc][2] - mnB);
                const float p3 = ex2(sc[mt][nc][3] - mnB);
                lA[mt] += p0 + p1; lB[mt] += p2 + p3;
                pp[mt][nc][0] = h2pack(p0, p1);
                pp[mt][nc][1] = h2pack(p2, p3);
            }
        }

        // ---- O += P*V : A-frags taken directly from pp ----
#pragma unroll
        for (int kb = 0; kb < 4; kb++) {
            const unsigned af0[4] = {pp[0][2 * kb][0], pp[0][2 * kb][1],
                                     pp[0][2 * kb + 1][0], pp[0][2 * kb + 1][1]};
            const unsigned af1[4] = {pp[1][2 * kb][0], pp[1][2 * kb][1],
                                     pp[1][2 * kb + 1][0], pp[1][2 * kb + 1][1]};
#pragma unroll
            for (int dp = 0; dp < 4; dp++) {
                unsigned bf[4];
                ldsm4t(bf, vsb + 4 * ((kb * 16 + lrow) * FS + dp * 8 + lcw));
                mma_fp16(o[0][2 * dp], af0, bf[0], bf[1]);
                mma_fp16(o[1][2 * dp], af1, bf[0], bf[1]);
                mma_fp16(o[0][2 * dp + 1], af0, bf[2], bf[3]);
                mma_fp16(o[1][2 * dp + 1], af1, bf[2], bf[3]);
            }
        }
    }

    // ---- epilogue ----
#pragma unroll
    for (int mt = 0; mt < 2; mt++) {
        float la = lA[mt], lb = lB[mt];
        la += __shfl_xor_sync(0xffffffffu, la, 1);
        la += __shfl_xor_sync(0xffffffffu, la, 2);
        lb += __shfl_xor_sync(0xffffffffu, lb, 1);
        lb += __shfl_xor_sync(0xffffffffu, lb, 2);
        const float ia = 1.f / la, ib = 1.f / lb;
        const int row = qt * 128 + wid * 32 + mt * 16 + r0;
        __half* oA = out + ((size_t)b * SEQ + row) * DIM + h * HEAD_DIM;
        __half* oB = oA + (size_t)8 * DIM;
#pragma unroll
        for (int nc = 0; nc < 8; nc++) {
            const int col = nc * 8 + 2 * q4;
            *(unsigned*)(oA + col) = h2pack(o[mt][nc][0] * ia, o[mt][nc][1] * ia);
            *(unsigned*)(oB + col) = h2pack(o[mt][nc][2] * ib, o[mt][nc][3] * ib);
        }
    }
}

// ===========================================================================
extern "C" void kernel_launch(void* const* d_in, const int* in_sizes, int n_in,
                              void* d_out, int out_size) {
    const float* x      = (const float*)d_in[0];
    const float* w_qkv  = (const float*)d_in[1];
    const float* b_qkv  = (const float*)d_in[2];
    const float* w_proj = (const float*)d_in[3];
    const float* b_proj = (const float*)d_in[4];
    float* out = (float*)d_out;

    __half *qkv, *att, *xh, *wq, *wp;
    cudaGetSymbolAddress((void**)&qkv, g_qkv);
    cudaGetSymbolAddress((void**)&att, g_att);
    cudaGetSymbolAddress((void**)&xh, g_xh);
    cudaGetSymbolAddress((void**)&wq, g_wqkv);
    cudaGetSymbolAddress((void**)&wp, g_wproj);

    const int M = BATCH * SEQ;               // 8192

    cudaFuncSetAttribute(gemm_h<1>, cudaFuncAttributeMaxDynamicSharedMemorySize,
                         GEMM_SMEM_B);
    cudaFuncSetAttribute(gemm_h<0>, cudaFuncAttributeMaxDynamicSharedMemorySize,
                         GEMM_SMEM_B);
    cudaFuncSetAttribute(flash_h, cudaFuncAttributeMaxDynamicSharedMemorySize,
                         FA_SMEM_B);

    f2h<<<(M * DIM) / 2048, 256>>>(x, xh);
    f2h<<<(QKV_DIM * DIM) / 2048, 256>>>(w_qkv, wq);
    f2h<<<(DIM * DIM) / 2048, 256>>>(w_proj, wp);

    {
        dim3 grid(QKV_DIM / 128, M / 128);   // (18, 64)
        gemm_h<1><<<grid, 128, GEMM_SMEM_B>>>(xh, wq, b_qkv, qkv,
                                              M, QKV_DIM, DIM, DIM);
    }
    {
        dim3 grid(SEQ / 128, HEADS, BATCH);  // (16, 12, 4)
        flash_h<<<grid, 128, FA_SMEM_B>>>(qkv, att);
    }
    {
        dim3 grid(DIM / 128, M / 128);       // (6, 64)
        gemm_h<0><<<grid, 128, GEMM_SMEM_B>>>(att, wp, b_proj, out,
                                              M, DIM, DIM, 0);
    }
}